// round 15
// baseline (speedup 1.0000x reference)
#include <cuda_runtime.h>
#include <cuda_bf16.h>
#include <cstdint>
#include <math.h>

#define NROW 8192
#define NE   262144
#define RPAD 128

// ---------------- scratch (static device arrays; no allocation) ----------------
__device__ __align__(16) float g_t[NROW * 256];   // x@W1+b1 (fp32)
__device__ __align__(16) float g_h[NROW * 256];   // tanh(spmm(t))
__device__ __align__(16) float g_g[NROW * 128];   // h@[Wmu|Wls]+b (fp32)
__device__ __align__(16) __nv_bfloat16 g_zhi[NROW * 64];
__device__ __align__(16) __nv_bfloat16 g_zlo[NROW * 64];
__device__ __align__(16) __nv_bfloat16 g_W1t_hi[256 * 512];  // W1^T bf16 hi
__device__ __align__(16) __nv_bfloat16 g_W1t_lo[256 * 512];  // W1^T bf16 lo
__device__ int   g_cursor[NROW];
__device__ __align__(16) int2 g_cw[NROW * RPAD];  // (col, weight-bits) padded buckets

// ---------------- fork/join stream + events (module-load init, capture-safe) ----
static cudaStream_t g_s2;
static cudaEvent_t  g_evF, g_evJ, g_evA, g_evG, g_evC, g_evE;
static struct _StreamInit {
    _StreamInit() {
        cudaStreamCreateWithFlags(&g_s2, cudaStreamNonBlocking);
        cudaEventCreateWithFlags(&g_evF, cudaEventDisableTiming);
        cudaEventCreateWithFlags(&g_evJ, cudaEventDisableTiming);
        cudaEventCreateWithFlags(&g_evA, cudaEventDisableTiming);
        cudaEventCreateWithFlags(&g_evG, cudaEventDisableTiming);
        cudaEventCreateWithFlags(&g_evC, cudaEventDisableTiming);
        cudaEventCreateWithFlags(&g_evE, cudaEventDisableTiming);
    }
} g_stream_init;

// ---------------- packed f32x2 helpers ----------
__device__ __forceinline__ unsigned long long dup2(float x) {
    unsigned long long u;
    asm("mov.b64 %0, {%1, %1};" : "=l"(u) : "f"(x));
    return u;
}
__device__ __forceinline__ void ffma2(unsigned long long& acc, unsigned long long a,
                                      unsigned long long b) {
    asm("fma.rn.f32x2 %0, %1, %2, %0;" : "+l"(acc) : "l"(a), "l"(b));
}
__device__ __forceinline__ float2 unpack2(unsigned long long u) {
    float2 v;
    asm("mov.b64 {%0, %1}, %2;" : "=f"(v.x), "=f"(v.y) : "l"(u));
    return v;
}

// ---------------- warp MMA helpers ----------
__device__ __forceinline__ uint32_t smem_u32(const void* p) {
    uint32_t a;
    asm("{ .reg .u64 t; cvta.to.shared.u64 t, %1; cvt.u32.u64 %0, t; }" : "=r"(a) : "l"(p));
    return a;
}
__device__ __forceinline__ void ldsm4(uint32_t& r0, uint32_t& r1, uint32_t& r2, uint32_t& r3,
                                      uint32_t addr) {
    asm volatile("ldmatrix.sync.aligned.m8n8.x4.shared.b16 {%0,%1,%2,%3}, [%4];"
                 : "=r"(r0), "=r"(r1), "=r"(r2), "=r"(r3) : "r"(addr));
}
__device__ __forceinline__ void mma16816(float* c, const uint32_t* a, const uint32_t* b) {
    asm volatile(
        "mma.sync.aligned.m16n8k16.row.col.f32.bf16.bf16.f32 "
        "{%0,%1,%2,%3}, {%4,%5,%6,%7}, {%8,%9}, {%0,%1,%2,%3};"
        : "+f"(c[0]), "+f"(c[1]), "+f"(c[2]), "+f"(c[3])
        : "r"(a[0]), "r"(a[1]), "r"(a[2]), "r"(a[3]), "r"(b[0]), "r"(b[1]));
}
__device__ __forceinline__ uint32_t packbf(__nv_bfloat16 a, __nv_bfloat16 b) {
    __nv_bfloat162 t(a, b);
    return *reinterpret_cast<uint32_t*>(&t);
}
__device__ __forceinline__ void stcs2(float* p, float a, float b) {
    asm volatile("st.global.cs.v2.f32 [%0], {%1, %2};" :: "l"(p), "f"(a), "f"(b) : "memory");
}
__device__ __forceinline__ void stcs4(float* p, float4 v) {
    asm volatile("st.global.cs.v4.f32 [%0], {%1, %2, %3, %4};"
                 :: "l"(p), "f"(v.x), "f"(v.y), "f"(v.z), "f"(v.w) : "memory");
}
#define SWZ128(x) ((x) ^ (((x) >> 3) & 0x70))

// ---------------- prep: W1 transpose + bf16 split, zero cursors ----------------
__global__ void k_prep(const float* __restrict__ W1) {
    int idx = blockIdx.x * 256 + threadIdx.x;
    if (idx < NROW) g_cursor[idx] = 0;
    int n = idx >> 9, k = idx & 511;
    float v = W1[k * 256 + n];
    __nv_bfloat16 h = __float2bfloat16(v);
    g_W1t_hi[idx] = h;
    g_W1t_lo[idx] = __float2bfloat16(v - __bfloat162float(h));
}

// ---------------- scatter into padded buckets ----------------
__global__ void k_scatter_pad(const int* __restrict__ src, const int* __restrict__ dst,
                              const float* __restrict__ w) {
    int i = blockIdx.x * 256 + threadIdx.x;
    if (i < NE) {
        int r = src[i];
        int slot = atomicAdd(&g_cursor[r], 1);
        if (slot < RPAD)
            g_cw[r * RPAD + slot] = make_int2(dst[i], __float_as_int(w[i]));
    }
}

// ---------------- GEMM1 via mma.sync bf16 split + register prefetch ----------------
#define G1_SMEM (2 * 16384 + 2 * 8192)
__global__ __launch_bounds__(256) void k_gemm1_mma(const float* __restrict__ x,
                                                   const float* __restrict__ b1) {
    extern __shared__ __align__(1024) char smem[];
    char* tAhi = smem;
    char* tAlo = smem + 16384;
    char* tBhi = smem + 32768;
    char* tBlo = smem + 40960;
    const int bn = blockIdx.x, bm = blockIdx.y;
    const int tid = threadIdx.x, wid = tid >> 5, lid = tid & 31;
    const int wm = wid >> 1, wn = wid & 1;
    const uint32_t sAhi = smem_u32(tAhi), sAlo = smem_u32(tAlo);
    const uint32_t sBhi = smem_u32(tBhi), sBlo = smem_u32(tBlo);

    float acc[2][4][4];
#pragma unroll
    for (int mt = 0; mt < 2; mt++)
#pragma unroll
        for (int nt = 0; nt < 4; nt++)
#pragma unroll
            for (int r = 0; r < 4; r++) acc[mt][nt][r] = 0.f;

    const int l7 = lid & 7, g2 = lid >> 3;

    float4 xa[8];
    uint4 bhr[2], blr[2];
#pragma unroll
    for (int p = 0; p < 8; p++) {
        int idx = tid + p * 256;
        int row = idx >> 4, q4 = idx & 15;
        xa[p] = *(const float4*)(x + (size_t)(bm * 128 + row) * 512 + q4 * 4);
    }
#pragma unroll
    for (int p = 0; p < 2; p++) {
        int idx = tid + p * 256;
        int row = idx >> 3, q = idx & 7;
        size_t gsrc = (size_t)(bn * 64 + row) * 512 + q * 8;
        bhr[p] = *(const uint4*)(g_W1t_hi + gsrc);
        blr[p] = *(const uint4*)(g_W1t_lo + gsrc);
    }

#pragma unroll
    for (int kt = 0; kt < 8; kt++) {
#pragma unroll
        for (int p = 0; p < 8; p++) {
            int idx = tid + p * 256;
            int row = idx >> 4, q4 = idx & 15;
            float4 v = xa[p];
            __nv_bfloat16 h0 = __float2bfloat16(v.x), h1 = __float2bfloat16(v.y);
            __nv_bfloat16 h2 = __float2bfloat16(v.z), h3 = __float2bfloat16(v.w);
            __nv_bfloat16 l0 = __float2bfloat16(v.x - __bfloat162float(h0));
            __nv_bfloat16 l1 = __float2bfloat16(v.y - __bfloat162float(h1));
            __nv_bfloat16 l2 = __float2bfloat16(v.z - __bfloat162float(h2));
            __nv_bfloat16 l3 = __float2bfloat16(v.w - __bfloat162float(h3));
            uint32_t off = SWZ128((uint32_t)(row * 128 + q4 * 8));
            *(uint2*)(tAhi + off) = make_uint2(packbf(h0, h1), packbf(h2, h3));
            *(uint2*)(tAlo + off) = make_uint2(packbf(l0, l1), packbf(l2, l3));
        }
#pragma unroll
        for (int p = 0; p < 2; p++) {
            int idx = tid + p * 256;
            int row = idx >> 3, q = idx & 7;
            uint32_t off = SWZ128((uint32_t)(row * 128 + q * 16));
            *(uint4*)(tBhi + off) = bhr[p];
            *(uint4*)(tBlo + off) = blr[p];
        }
        __syncthreads();

        if (kt < 7) {
            const int k0 = (kt + 1) * 64;
#pragma unroll
            for (int p = 0; p < 8; p++) {
                int idx = tid + p * 256;
                int row = idx >> 4, q4 = idx & 15;
                xa[p] = *(const float4*)(x + (size_t)(bm * 128 + row) * 512 + k0 + q4 * 4);
            }
#pragma unroll
            for (int p = 0; p < 2; p++) {
                int idx = tid + p * 256;
                int row = idx >> 3, q = idx & 7;
                size_t gsrc = (size_t)(bn * 64 + row) * 512 + k0 + q * 8;
                bhr[p] = *(const uint4*)(g_W1t_hi + gsrc);
                blr[p] = *(const uint4*)(g_W1t_lo + gsrc);
            }
        }

#pragma unroll
        for (int ks = 0; ks < 4; ks++) {
            uint32_t ahi[2][4], alo[2][4];
#pragma unroll
            for (int mt = 0; mt < 2; mt++) {
                int row = wm * 32 + mt * 16 + ((g2 & 1) << 3) + l7;
                int q   = ks * 2 + (g2 >> 1);
                uint32_t off = SWZ128((uint32_t)(row * 128 + q * 16));
                ldsm4(ahi[mt][0], ahi[mt][1], ahi[mt][2], ahi[mt][3], sAhi + off);
                ldsm4(alo[mt][0], alo[mt][1], alo[mt][2], alo[mt][3], sAlo + off);
            }
#pragma unroll
            for (int ntp = 0; ntp < 2; ntp++) {
                int nrow = wn * 32 + ntp * 16 + ((g2 >> 1) << 3) + l7;
                int q    = ks * 2 + (g2 & 1);
                uint32_t off = SWZ128((uint32_t)(nrow * 128 + q * 16));
                uint32_t bh[4], bl[4];
                ldsm4(bh[0], bh[1], bh[2], bh[3], sBhi + off);
                ldsm4(bl[0], bl[1], bl[2], bl[3], sBlo + off);
                int nt0 = ntp * 2, nt1 = ntp * 2 + 1;
#pragma unroll
                for (int mt = 0; mt < 2; mt++) {
                    mma16816(acc[mt][nt0], ahi[mt], bh + 0);
                    mma16816(acc[mt][nt1], ahi[mt], bh + 2);
                    mma16816(acc[mt][nt0], ahi[mt], bl + 0);
                    mma16816(acc[mt][nt1], ahi[mt], bl + 2);
                    mma16816(acc[mt][nt0], alo[mt], bh + 0);
                    mma16816(acc[mt][nt1], alo[mt], bh + 2);
                }
            }
        }
        __syncthreads();
    }

    const int lg = lid >> 2, lt = lid & 3;
#pragma unroll
    for (int mt = 0; mt < 2; mt++) {
        size_t r0 = (size_t)(bm * 128 + wm * 32 + mt * 16 + lg);
        int cbase = bn * 64 + wn * 32 + 2 * lt;
        float* row0 = g_t + r0 * 256 + cbase;
        float* row1 = row0 + 8 * 256;
#pragma unroll
        for (int nt = 0; nt < 4; nt++) {
            float2 bv = *(const float2*)(b1 + cbase + nt * 8);
            *(float2*)(row0 + nt * 8) = make_float2(acc[mt][nt][0] + bv.x, acc[mt][nt][1] + bv.y);
            *(float2*)(row1 + nt * 8) = make_float2(acc[mt][nt][2] + bv.x, acc[mt][nt][3] + bv.y);
        }
    }
}

// ---------------- GEMM2: M=64 tiles; bm_base selects row-half ----------------
__global__ __launch_bounds__(256) void k_gemm2(const float* __restrict__ Wmu,
                                               const float* __restrict__ bmu,
                                               const float* __restrict__ Wls,
                                               const float* __restrict__ bls,
                                               int bm_base) {
    __shared__ float As[16 * 64];
    __shared__ float Bs[16 * 64];
    const int bm = blockIdx.y + bm_base, bn = blockIdx.x;
    const float* W = (bn == 0) ? Wmu : Wls;
    const float* bb = (bn == 0) ? bmu : bls;
    const int tid = threadIdx.x;
    const int ty = tid >> 4, tx = tid & 15;
    const int row0 = ty * 4, col0 = tx * 4;

    unsigned long long acc[2][4];
    {
        float4 bv = *(const float4*)(bb + col0);
        acc[0][0] = dup2(bv.x); acc[0][1] = dup2(bv.y); acc[0][2] = dup2(bv.z); acc[0][3] = dup2(bv.w);
        acc[1][0] = acc[0][0]; acc[1][1] = acc[0][1]; acc[1][2] = acc[0][2]; acc[1][3] = acc[0][3];
    }

    for (int kt = 0; kt < 16; kt++) {
        {
            int ar = tid >> 2, kq = tid & 3;
            float4 v = *(const float4*)(g_h + (size_t)(bm * 64 + ar) * 256 + kt * 16 + kq * 4);
            int rs = ar ^ (kq << 3);
            As[(kq * 4 + 0) * 64 + rs] = v.x;
            As[(kq * 4 + 1) * 64 + rs] = v.y;
            As[(kq * 4 + 2) * 64 + rs] = v.z;
            As[(kq * 4 + 3) * 64 + rs] = v.w;
        }
        {
            int kr = tid >> 4, cq = tid & 15;
            *(float4*)&Bs[kr * 64 + cq * 4] =
                *(const float4*)(W + (size_t)(kt * 16 + kr) * 64 + cq * 4);
        }
        __syncthreads();
#pragma unroll
        for (int k = 0; k < 16; k++) {
            const float* ab = &As[k * 64 + (row0 ^ ((k >> 2) << 3))];
            unsigned long long a0 = *(const unsigned long long*)(ab + 0);
            unsigned long long a1 = *(const unsigned long long*)(ab + 2);
            float4 b = *(const float4*)&Bs[k * 64 + col0];
            unsigned long long bx = dup2(b.x), by = dup2(b.y), bz = dup2(b.z), bw = dup2(b.w);
            ffma2(acc[0][0], a0, bx); ffma2(acc[0][1], a0, by);
            ffma2(acc[0][2], a0, bz); ffma2(acc[0][3], a0, bw);
            ffma2(acc[1][0], a1, bx); ffma2(acc[1][1], a1, by);
            ffma2(acc[1][2], a1, bz); ffma2(acc[1][3], a1, bw);
        }
        __syncthreads();
    }
    float* Cp = g_g + (size_t)(bm * 64 + row0) * 128 + bn * 64 + col0;
#pragma unroll
    for (int p = 0; p < 2; p++) {
        float2 t0 = unpack2(acc[p][0]), t1 = unpack2(acc[p][1]);
        float2 t2 = unpack2(acc[p][2]), t3 = unpack2(acc[p][3]);
        *(float4*)(Cp + (size_t)(2 * p) * 128)     = make_float4(t0.x, t1.x, t2.x, t3.x);
        *(float4*)(Cp + (size_t)(2 * p + 1) * 128) = make_float4(t0.y, t1.y, t2.y, t3.y);
    }
}

// ---------------- SpMM1 + tanh: block 64, float4/thread; row_base selects half ----
__global__ void k_spmm1(int row_base) {
    int r = blockIdx.x + row_base, tid = threadIdx.x;
    int e = g_cursor[r];
    if (e > RPAD) e = RPAD;
    const int4* cw4 = (const int4*)(g_cw + r * RPAD);
    const float4* T = (const float4*)g_t;
    float4 acc = make_float4(0.f, 0.f, 0.f, 0.f);
    int p = 0;
    for (; p + 8 <= e; p += 8) {
        int4 e01 = cw4[(p >> 1) + 0];
        int4 e23 = cw4[(p >> 1) + 1];
        int4 e45 = cw4[(p >> 1) + 2];
        int4 e67 = cw4[(p >> 1) + 3];
        float4 v0 = T[e01.x * 64 + tid];
        float4 v1 = T[e01.z * 64 + tid];
        float4 v2 = T[e23.x * 64 + tid];
        float4 v3 = T[e23.z * 64 + tid];
        float4 v4 = T[e45.x * 64 + tid];
        float4 v5 = T[e45.z * 64 + tid];
        float4 v6 = T[e67.x * 64 + tid];
        float4 v7 = T[e67.z * 64 + tid];
        float w0 = __int_as_float(e01.y), w1 = __int_as_float(e01.w);
        float w2 = __int_as_float(e23.y), w3 = __int_as_float(e23.w);
        float w4 = __int_as_float(e45.y), w5 = __int_as_float(e45.w);
        float w6 = __int_as_float(e67.y), w7 = __int_as_float(e67.w);
        acc.x = fmaf(w0, v0.x, acc.x); acc.y = fmaf(w0, v0.y, acc.y);
        acc.z = fmaf(w0, v0.z, acc.z); acc.w = fmaf(w0, v0.w, acc.w);
        acc.x = fmaf(w1, v1.x, acc.x); acc.y = fmaf(w1, v1.y, acc.y);
        acc.z = fmaf(w1, v1.z, acc.z); acc.w = fmaf(w1, v1.w, acc.w);
        acc.x = fmaf(w2, v2.x, acc.x); acc.y = fmaf(w2, v2.y, acc.y);
        acc.z = fmaf(w2, v2.z, acc.z); acc.w = fmaf(w2, v2.w, acc.w);
        acc.x = fmaf(w3, v3.x, acc.x); acc.y = fmaf(w3, v3.y, acc.y);
        acc.z = fmaf(w3, v3.z, acc.z); acc.w = fmaf(w3, v3.w, acc.w);
        acc.x = fmaf(w4, v4.x, acc.x); acc.y = fmaf(w4, v4.y, acc.y);
        acc.z = fmaf(w4, v4.z, acc.z); acc.w = fmaf(w4, v4.w, acc.w);
        acc.x = fmaf(w5, v5.x, acc.x); acc.y = fmaf(w5, v5.y, acc.y);
        acc.z = fmaf(w5, v5.z, acc.z); acc.w = fmaf(w5, v5.w, acc.w);
        acc.x = fmaf(w6, v6.x, acc.x); acc.y = fmaf(w6, v6.y, acc.y);
        acc.z = fmaf(w6, v6.z, acc.z); acc.w = fmaf(w6, v6.w, acc.w);
        acc.x = fmaf(w7, v7.x, acc.x); acc.y = fmaf(w7, v7.y, acc.y);
        acc.z = fmaf(w7, v7.z, acc.z); acc.w = fmaf(w7, v7.w, acc.w);
    }
    const int2* cw = g_cw + r * RPAD;
    for (; p < e; p++) {
        int2 a = cw[p];
        float w = __int_as_float(a.y);
        float4 v = T[a.x * 64 + tid];
        acc.x = fmaf(w, v.x, acc.x); acc.y = fmaf(w, v.y, acc.y);
        acc.z = fmaf(w, v.z, acc.z); acc.w = fmaf(w, v.w, acc.w);
    }
    ((float4*)g_h)[r * 64 + tid] =
        make_float4(tanhf(acc.x), tanhf(acc.y), tanhf(acc.z), tanhf(acc.w));
}

// ---------------- SpMM2 + reparam + bf16 split; row_base selects half ----------
__global__ void k_spmm2(const float* __restrict__ eps, float* __restrict__ oz,
                        float* __restrict__ omu, float* __restrict__ ols, int row_base) {
    int r = blockIdx.x + row_base, tid = threadIdx.x;
    int e = g_cursor[r];
    if (e > RPAD) e = RPAD;
    const int4* cw4 = (const int4*)(g_cw + r * RPAD);
    const float2* G = (const float2*)g_g;
    float2 acc = make_float2(0.f, 0.f);
    int p = 0;
    for (; p + 8 <= e; p += 8) {
        int4 e01 = cw4[(p >> 1) + 0];
        int4 e23 = cw4[(p >> 1) + 1];
        int4 e45 = cw4[(p >> 1) + 2];
        int4 e67 = cw4[(p >> 1) + 3];
        float2 v0 = G[e01.x * 64 + tid];
        float2 v1 = G[e01.z * 64 + tid];
        float2 v2 = G[e23.x * 64 + tid];
        float2 v3 = G[e23.z * 64 + tid];
        float2 v4 = G[e45.x * 64 + tid];
        float2 v5 = G[e45.z * 64 + tid];
        float2 v6 = G[e67.x * 64 + tid];
        float2 v7 = G[e67.z * 64 + tid];
        float w0 = __int_as_float(e01.y), w1 = __int_as_float(e01.w);
        float w2 = __int_as_float(e23.y), w3 = __int_as_float(e23.w);
        float w4 = __int_as_float(e45.y), w5 = __int_as_float(e45.w);
        float w6 = __int_as_float(e67.y), w7 = __int_as_float(e67.w);
        acc.x = fmaf(w0, v0.x, acc.x); acc.y = fmaf(w0, v0.y, acc.y);
        acc.x = fmaf(w1, v1.x, acc.x); acc.y = fmaf(w1, v1.y, acc.y);
        acc.x = fmaf(w2, v2.x, acc.x); acc.y = fmaf(w2, v2.y, acc.y);
        acc.x = fmaf(w3, v3.x, acc.x); acc.y = fmaf(w3, v3.y, acc.y);
        acc.x = fmaf(w4, v4.x, acc.x); acc.y = fmaf(w4, v4.y, acc.y);
        acc.x = fmaf(w5, v5.x, acc.x); acc.y = fmaf(w5, v5.y, acc.y);
        acc.x = fmaf(w6, v6.x, acc.x); acc.y = fmaf(w6, v6.y, acc.y);
        acc.x = fmaf(w7, v7.x, acc.x); acc.y = fmaf(w7, v7.y, acc.y);
    }
    const int2* cw = g_cw + r * RPAD;
    for (; p < e; p++) {
        int2 a = cw[p];
        float w = __int_as_float(a.y);
        float2 v = G[a.x * 64 + tid];
        acc.x = fmaf(w, v.x, acc.x); acc.y = fmaf(w, v.y, acc.y);
    }
    __shared__ float sm[128];
    sm[2 * tid]     = acc.x;
    sm[2 * tid + 1] = acc.y;
    __syncthreads();
    if (tid < 32) {
        float2 mu = *(const float2*)&sm[2 * tid];
        float2 ls = *(const float2*)&sm[2 * tid + 64];
        float2 ep = ((const float2*)(eps + (size_t)r * 64))[tid];
        float z0 = fmaf(ep.x, expf(ls.x), mu.x);
        float z1 = fmaf(ep.y, expf(ls.y), mu.y);
        ((float2*)(omu + (size_t)r * 64))[tid] = mu;
        ((float2*)(ols + (size_t)r * 64))[tid] = ls;
        ((float2*)(oz  + (size_t)r * 64))[tid] = make_float2(z0, z1);
        __nv_bfloat16 zh0 = __float2bfloat16(z0);
        __nv_bfloat16 zh1 = __float2bfloat16(z1);
        ((__nv_bfloat162*)g_zhi)[r * 32 + tid] = __nv_bfloat162(zh0, zh1);
        ((__nv_bfloat162*)g_zlo)[r * 32 + tid] = __nv_bfloat162(
            __float2bfloat16(z0 - __bfloat162float(zh0)),
            __float2bfloat16(z1 - __bfloat162float(zh1)));
    }
}

// ---------------- z @ z^T: triangular, split quad (bi,bj<32) vs rest ----------
#define ZZT_SMEM (4 * 16384)
__global__ __launch_bounds__(256, 2) void k_zzt_mma(float* __restrict__ C, int mode) {
    extern __shared__ __align__(1024) char smem[];
    char* tAhi = smem;
    char* tAlo = smem + 16384;
    char* tBhi = smem + 32768;
    char* tBlo = smem + 49152;
    int bi, bj;
    if (mode == 0) {           // quad: bi<=bj<32, 528 tiles
        int rem = blockIdx.x;
        bi = 0;
        while (rem >= 32 - bi) { rem -= 32 - bi; bi++; }
        bj = bi + rem;
    } else {                   // rest: bj in [32,64), bi<=bj, 1552 tiles
        int rem = blockIdx.x;
        bj = 32;
        while (rem >= bj + 1) { rem -= bj + 1; bj++; }
        bi = rem;
    }
    const int tid = threadIdx.x, wid = tid >> 5, lid = tid & 31;

    {
        const uint4* ghi_a = (const uint4*)(g_zhi + (size_t)bi * 128 * 64);
        const uint4* glo_a = (const uint4*)(g_zlo + (size_t)bi * 128 * 64);
        const uint4* ghi_b = (const uint4*)(g_zhi + (size_t)bj * 128 * 64);
        const uint4* glo_b = (const uint4*)(g_zlo + (size_t)bj * 128 * 64);
#pragma unroll
        for (int p = 0; p < 4; p++) {
            int idx = tid + p * 256;
            int row = idx >> 3, q = idx & 7;
            uint32_t off = SWZ128((uint32_t)(row * 128 + q * 16));
            *(uint4*)(tAhi + off) = ghi_a[idx];
            *(uint4*)(tAlo + off) = glo_a[idx];
            *(uint4*)(tBhi + off) = ghi_b[idx];
            *(uint4*)(tBlo + off) = glo_b[idx];
        }
    }
    __syncthreads();

    const int wm = wid >> 1, wn = wid & 1;
    const uint32_t sAhi = smem_u32(tAhi), sAlo = smem_u32(tAlo);
    const uint32_t sBhi = smem_u32(tBhi), sBlo = smem_u32(tBlo);

    float acc[2][8][4];
#pragma unroll
    for (int mt = 0; mt < 2; mt++)
#pragma unroll
        for (int nt = 0; nt < 8; nt++)
#pragma unroll
            for (int r = 0; r < 4; r++) acc[mt][nt][r] = 0.f;

    const int l7 = lid & 7, g2 = lid >> 3;

#pragma unroll
    for (int ks = 0; ks < 4; ks++) {
        uint32_t ahi[2][4], alo[2][4];
#pragma unroll
        for (int mt = 0; mt < 2; mt++) {
            int row = wm * 32 + mt * 16 + ((g2 & 1) << 3) + l7;
            int q   = ks * 2 + (g2 >> 1);
            uint32_t off = SWZ128((uint32_t)(row * 128 + q * 16));
            ldsm4(ahi[mt][0], ahi[mt][1], ahi[mt][2], ahi[mt][3], sAhi + off);
            ldsm4(alo[mt][0], alo[mt][1], alo[mt][2], alo[mt][3], sAlo + off);
        }
#pragma unroll
        for (int ntp = 0; ntp < 4; ntp++) {
            int nrow = wn * 64 + ntp * 16 + ((g2 >> 1) << 3) + l7;
            int q    = ks * 2 + (g2 & 1);
            uint32_t off = SWZ128((uint32_t)(nrow * 128 + q * 16));
            uint32_t bh[4], bl[4];
            ldsm4(bh[0], bh[1], bh[2], bh[3], sBhi + off);
            ldsm4(bl[0], bl[1], bl[2], bl[3], sBlo + off);
            int nt0 = ntp * 2, nt1 = ntp * 2 + 1;
#pragma unroll
            for (int mt = 0; mt < 2; mt++) {
                mma16816(acc[mt][nt0], ahi[mt], bh + 0);
                mma16816(acc[mt][nt1], ahi[mt], bh + 2);
                mma16816(acc[mt][nt0], ahi[mt], bl + 0);
                mma16816(acc[mt][nt1], ahi[mt], bl + 2);
                mma16816(acc[mt][nt0], alo[mt], bh + 0);
                mma16816(acc[mt][nt1], alo[mt], bh + 2);
            }
        }
    }

    const int lg = lid >> 2, lt = lid & 3;
#pragma unroll
    for (int mt = 0; mt < 2; mt++) {
        size_t r0 = (size_t)(bi * 128 + wm * 32 + mt * 16 + lg);
        float* row0 = C + r0 * NROW + bj * 128 + wn * 64 + 2 * lt;
        float* row1 = row0 + 8 * (size_t)NROW;
#pragma unroll
        for (int nt = 0; nt < 8; nt++) {
            stcs2(row0 + nt * 8, acc[mt][nt][0], acc[mt][nt][1]);
            stcs2(row1 + nt * 8, acc[mt][nt][2], acc[mt][nt][3]);
        }
    }

    if (bi != bj) {
        __syncthreads();
        float* smT = (float*)smem;
#pragma unroll
        for (int mt = 0; mt < 2; mt++) {
#pragma unroll
            for (int nt = 0; nt < 8; nt++) {
#pragma unroll
                for (int r = 0; r < 4; r++) {
                    int ri = wm * 32 + mt * 16 + lg + ((r >> 1) << 3);
                    int cj = wn * 64 + nt * 8 + 2 * lt + (r & 1);
                    smT[cj * 128 + (ri ^ ((cj & 7) << 3))] = acc[mt][nt][r];
                }
            }
        }
        __syncthreads();
#pragma unroll
        for (int p = 0; p < 16; p++) {
            int idx = tid + p * 256;
            int mr = idx >> 5, q = idx & 31;
            int ri0 = (q * 4) ^ ((mr & 7) << 3);
            float4 v = *(const float4*)&smT[mr * 128 + ri0];
            stcs4(C + (size_t)(bj * 128 + mr) * NROW + bi * 128 + (q * 4), v);
        }
    }
}

// ---------------- launch: two-stream pipelined schedule ----------------
extern "C" void kernel_launch(void* const* d_in, const int* in_sizes, int n_in,
                              void* d_out, int out_size) {
    const float* x    = (const float*)d_in[0];
    const int*   esrc = (const int*)d_in[1];
    const int*   edst = (const int*)d_in[2];
    const float* ew   = (const float*)d_in[3];
    const float* eps  = (const float*)d_in[4];
    const float* W1   = (const float*)d_in[5];
    const float* b1   = (const float*)d_in[6];
    const float* Wmu  = (const float*)d_in[7];
    const float* bmu  = (const float*)d_in[8];
    const float* Wls  = (const float*)d_in[9];
    const float* bls  = (const float*)d_in[10];

    float* out  = (float*)d_out;
    float* oz   = out;
    float* oadj = out + (size_t)NROW * 64;
    float* omu  = oadj + (size_t)NROW * NROW;
    float* ols  = omu + (size_t)NROW * 64;

    cudaFuncSetAttribute(k_zzt_mma, cudaFuncAttributeMaxDynamicSharedMemorySize, ZZT_SMEM);
    cudaFuncSetAttribute(k_gemm1_mma, cudaFuncAttributeMaxDynamicSharedMemorySize, G1_SMEM);

    k_prep<<<512, 256>>>(W1);

    // fork 1: gemm1 (s2) || scatter (main)
    cudaEventRecord(g_evF, 0);
    cudaStreamWaitEvent(g_s2, g_evF, 0);
    k_gemm1_mma<<<dim3(4, 64), 256, G1_SMEM, g_s2>>>(x, b1);
    k_scatter_pad<<<NE / 256, 256>>>(esrc, edst, ew);
    cudaEventRecord(g_evJ, g_s2);
    cudaStreamWaitEvent(0, g_evJ, 0);

    // spmm1 half 1, then fork 2: gemm2 half1 (s2) || spmm1 half2 (main)
    k_spmm1<<<NROW / 2, 64>>>(0);
    cudaEventRecord(g_evA, 0);
    cudaStreamWaitEvent(g_s2, g_evA, 0);
    k_gemm2<<<dim3(2, 64), 256, 0, g_s2>>>(Wmu, bmu, Wls, bls, 0);
    cudaEventRecord(g_evG, g_s2);
    k_spmm1<<<NROW / 2, 64>>>(NROW / 2);
    k_gemm2<<<dim3(2, 64), 256>>>(Wmu, bmu, Wls, bls, 64);
    cudaStreamWaitEvent(0, g_evG, 0);

    // spmm2 half 1, then fork 3: zzt quad (s2) || spmm2 half2 + zzt rest (main)
    k_spmm2<<<NROW / 2, 64>>>(eps, oz, omu, ols, 0);
    cudaEventRecord(g_evC, 0);
    cudaStreamWaitEvent(g_s2, g_evC, 0);
    k_zzt_mma<<<528, 256, ZZT_SMEM, g_s2>>>(oadj, 0);
    cudaEventRecord(g_evE, g_s2);
    k_spmm2<<<NROW / 2, 64>>>(eps, oz, omu, ols, NROW / 2);
    k_zzt_mma<<<1552, 256, ZZT_SMEM>>>(oadj, 1);
    cudaStreamWaitEvent(0, g_evE, 0);
}

// round 16
// speedup vs baseline: 1.0808x; 1.0808x over previous
#include <cuda_runtime.h>
#include <cuda_bf16.h>
#include <cstdint>
#include <math.h>

#define NROW 8192
#define NE   262144
#define RPAD 128

// ---------------- scratch (static device arrays; no allocation) ----------------
__device__ __align__(16) float g_t[NROW * 256];   // x@W1+b1 (fp32)
__device__ __align__(16) float g_h[NROW * 256];   // tanh(spmm(t))
__device__ __align__(16) float g_g[NROW * 128];   // h@[Wmu|Wls]+b (fp32)
__device__ __align__(16) __nv_bfloat16 g_zhi[NROW * 64];
__device__ __align__(16) __nv_bfloat16 g_zlo[NROW * 64];
__device__ __align__(16) __nv_bfloat16 g_W1t_hi[256 * 512];  // W1^T bf16 hi
__device__ __align__(16) __nv_bfloat16 g_W1t_lo[256 * 512];  // W1^T bf16 lo
__device__ int   g_cursor[NROW];
__device__ __align__(16) int2 g_cw[NROW * RPAD];  // (col, weight-bits) padded buckets

// ---------------- fork/join stream + events (module-load init, capture-safe) ----
static cudaStream_t g_s2;
static cudaEvent_t  g_evF, g_evJ;
static struct _StreamInit {
    _StreamInit() {
        cudaStreamCreateWithFlags(&g_s2, cudaStreamNonBlocking);
        cudaEventCreateWithFlags(&g_evF, cudaEventDisableTiming);
        cudaEventCreateWithFlags(&g_evJ, cudaEventDisableTiming);
    }
} g_stream_init;

// ---------------- packed f32x2 helpers ----------
__device__ __forceinline__ unsigned long long dup2(float x) {
    unsigned long long u;
    asm("mov.b64 %0, {%1, %1};" : "=l"(u) : "f"(x));
    return u;
}
__device__ __forceinline__ void ffma2(unsigned long long& acc, unsigned long long a,
                                      unsigned long long b) {
    asm("fma.rn.f32x2 %0, %1, %2, %0;" : "+l"(acc) : "l"(a), "l"(b));
}
__device__ __forceinline__ float2 unpack2(unsigned long long u) {
    float2 v;
    asm("mov.b64 {%0, %1}, %2;" : "=f"(v.x), "=f"(v.y) : "l"(u));
    return v;
}

// ---------------- warp MMA helpers ----------
__device__ __forceinline__ uint32_t smem_u32(const void* p) {
    uint32_t a;
    asm("{ .reg .u64 t; cvta.to.shared.u64 t, %1; cvt.u32.u64 %0, t; }" : "=r"(a) : "l"(p));
    return a;
}
__device__ __forceinline__ void ldsm4(uint32_t& r0, uint32_t& r1, uint32_t& r2, uint32_t& r3,
                                      uint32_t addr) {
    asm volatile("ldmatrix.sync.aligned.m8n8.x4.shared.b16 {%0,%1,%2,%3}, [%4];"
                 : "=r"(r0), "=r"(r1), "=r"(r2), "=r"(r3) : "r"(addr));
}
__device__ __forceinline__ void mma16816(float* c, const uint32_t* a, const uint32_t* b) {
    asm volatile(
        "mma.sync.aligned.m16n8k16.row.col.f32.bf16.bf16.f32 "
        "{%0,%1,%2,%3}, {%4,%5,%6,%7}, {%8,%9}, {%0,%1,%2,%3};"
        : "+f"(c[0]), "+f"(c[1]), "+f"(c[2]), "+f"(c[3])
        : "r"(a[0]), "r"(a[1]), "r"(a[2]), "r"(a[3]), "r"(b[0]), "r"(b[1]));
}
__device__ __forceinline__ uint32_t packbf(__nv_bfloat16 a, __nv_bfloat16 b) {
    __nv_bfloat162 t(a, b);
    return *reinterpret_cast<uint32_t*>(&t);
}
__device__ __forceinline__ void stcs2(float* p, float a, float b) {
    asm volatile("st.global.cs.v2.f32 [%0], {%1, %2};" :: "l"(p), "f"(a), "f"(b) : "memory");
}
__device__ __forceinline__ void stcs4(float* p, float4 v) {
    asm volatile("st.global.cs.v4.f32 [%0], {%1, %2, %3, %4};"
                 :: "l"(p), "f"(v.x), "f"(v.y), "f"(v.z), "f"(v.w) : "memory");
}
#define SWZ128(x) ((x) ^ (((x) >> 3) & 0x70))

// ---------------- prep: W1 transpose + bf16 split, zero cursors ----------------
__global__ void k_prep(const float* __restrict__ W1) {
    int idx = blockIdx.x * 256 + threadIdx.x;
    if (idx < NROW) g_cursor[idx] = 0;
    int n = idx >> 9, k = idx & 511;
    float v = W1[k * 256 + n];
    __nv_bfloat16 h = __float2bfloat16(v);
    g_W1t_hi[idx] = h;
    g_W1t_lo[idx] = __float2bfloat16(v - __bfloat162float(h));
}

// ---------------- scatter into padded buckets ----------------
__global__ void k_scatter_pad(const int* __restrict__ src, const int* __restrict__ dst,
                              const float* __restrict__ w) {
    int i = blockIdx.x * 256 + threadIdx.x;
    if (i < NE) {
        int r = src[i];
        int slot = atomicAdd(&g_cursor[r], 1);
        if (slot < RPAD)
            g_cw[r * RPAD + slot] = make_int2(dst[i], __float_as_int(w[i]));
    }
}

// ---------------- GEMM1 via mma.sync bf16 split + register prefetch ----------------
#define G1_SMEM (2 * 16384 + 2 * 8192)
__global__ __launch_bounds__(256) void k_gemm1_mma(const float* __restrict__ x,
                                                   const float* __restrict__ b1) {
    extern __shared__ __align__(1024) char smem[];
    char* tAhi = smem;
    char* tAlo = smem + 16384;
    char* tBhi = smem + 32768;
    char* tBlo = smem + 40960;
    const int bn = blockIdx.x, bm = blockIdx.y;
    const int tid = threadIdx.x, wid = tid >> 5, lid = tid & 31;
    const int wm = wid >> 1, wn = wid & 1;
    const uint32_t sAhi = smem_u32(tAhi), sAlo = smem_u32(tAlo);
    const uint32_t sBhi = smem_u32(tBhi), sBlo = smem_u32(tBlo);

    float acc[2][4][4];
#pragma unroll
    for (int mt = 0; mt < 2; mt++)
#pragma unroll
        for (int nt = 0; nt < 4; nt++)
#pragma unroll
            for (int r = 0; r < 4; r++) acc[mt][nt][r] = 0.f;

    const int l7 = lid & 7, g2 = lid >> 3;

    float4 xa[8];
    uint4 bhr[2], blr[2];
#pragma unroll
    for (int p = 0; p < 8; p++) {
        int idx = tid + p * 256;
        int row = idx >> 4, q4 = idx & 15;
        xa[p] = *(const float4*)(x + (size_t)(bm * 128 + row) * 512 + q4 * 4);
    }
#pragma unroll
    for (int p = 0; p < 2; p++) {
        int idx = tid + p * 256;
        int row = idx >> 3, q = idx & 7;
        size_t gsrc = (size_t)(bn * 64 + row) * 512 + q * 8;
        bhr[p] = *(const uint4*)(g_W1t_hi + gsrc);
        blr[p] = *(const uint4*)(g_W1t_lo + gsrc);
    }

#pragma unroll
    for (int kt = 0; kt < 8; kt++) {
#pragma unroll
        for (int p = 0; p < 8; p++) {
            int idx = tid + p * 256;
            int row = idx >> 4, q4 = idx & 15;
            float4 v = xa[p];
            __nv_bfloat16 h0 = __float2bfloat16(v.x), h1 = __float2bfloat16(v.y);
            __nv_bfloat16 h2 = __float2bfloat16(v.z), h3 = __float2bfloat16(v.w);
            __nv_bfloat16 l0 = __float2bfloat16(v.x - __bfloat162float(h0));
            __nv_bfloat16 l1 = __float2bfloat16(v.y - __bfloat162float(h1));
            __nv_bfloat16 l2 = __float2bfloat16(v.z - __bfloat162float(h2));
            __nv_bfloat16 l3 = __float2bfloat16(v.w - __bfloat162float(h3));
            uint32_t off = SWZ128((uint32_t)(row * 128 + q4 * 8));
            *(uint2*)(tAhi + off) = make_uint2(packbf(h0, h1), packbf(h2, h3));
            *(uint2*)(tAlo + off) = make_uint2(packbf(l0, l1), packbf(l2, l3));
        }
#pragma unroll
        for (int p = 0; p < 2; p++) {
            int idx = tid + p * 256;
            int row = idx >> 3, q = idx & 7;
            uint32_t off = SWZ128((uint32_t)(row * 128 + q * 16));
            *(uint4*)(tBhi + off) = bhr[p];
            *(uint4*)(tBlo + off) = blr[p];
        }
        __syncthreads();

        if (kt < 7) {
            const int k0 = (kt + 1) * 64;
#pragma unroll
            for (int p = 0; p < 8; p++) {
                int idx = tid + p * 256;
                int row = idx >> 4, q4 = idx & 15;
                xa[p] = *(const float4*)(x + (size_t)(bm * 128 + row) * 512 + k0 + q4 * 4);
            }
#pragma unroll
            for (int p = 0; p < 2; p++) {
                int idx = tid + p * 256;
                int row = idx >> 3, q = idx & 7;
                size_t gsrc = (size_t)(bn * 64 + row) * 512 + k0 + q * 8;
                bhr[p] = *(const uint4*)(g_W1t_hi + gsrc);
                blr[p] = *(const uint4*)(g_W1t_lo + gsrc);
            }
        }

#pragma unroll
        for (int ks = 0; ks < 4; ks++) {
            uint32_t ahi[2][4], alo[2][4];
#pragma unroll
            for (int mt = 0; mt < 2; mt++) {
                int row = wm * 32 + mt * 16 + ((g2 & 1) << 3) + l7;
                int q   = ks * 2 + (g2 >> 1);
                uint32_t off = SWZ128((uint32_t)(row * 128 + q * 16));
                ldsm4(ahi[mt][0], ahi[mt][1], ahi[mt][2], ahi[mt][3], sAhi + off);
                ldsm4(alo[mt][0], alo[mt][1], alo[mt][2], alo[mt][3], sAlo + off);
            }
#pragma unroll
            for (int ntp = 0; ntp < 2; ntp++) {
                int nrow = wn * 32 + ntp * 16 + ((g2 >> 1) << 3) + l7;
                int q    = ks * 2 + (g2 & 1);
                uint32_t off = SWZ128((uint32_t)(nrow * 128 + q * 16));
                uint32_t bh[4], bl[4];
                ldsm4(bh[0], bh[1], bh[2], bh[3], sBhi + off);
                ldsm4(bl[0], bl[1], bl[2], bl[3], sBlo + off);
                int nt0 = ntp * 2, nt1 = ntp * 2 + 1;
#pragma unroll
                for (int mt = 0; mt < 2; mt++) {
                    mma16816(acc[mt][nt0], ahi[mt], bh + 0);
                    mma16816(acc[mt][nt1], ahi[mt], bh + 2);
                    mma16816(acc[mt][nt0], ahi[mt], bl + 0);
                    mma16816(acc[mt][nt1], ahi[mt], bl + 2);
                    mma16816(acc[mt][nt0], alo[mt], bh + 0);
                    mma16816(acc[mt][nt1], alo[mt], bh + 2);
                }
            }
        }
        __syncthreads();
    }

    const int lg = lid >> 2, lt = lid & 3;
#pragma unroll
    for (int mt = 0; mt < 2; mt++) {
        size_t r0 = (size_t)(bm * 128 + wm * 32 + mt * 16 + lg);
        int cbase = bn * 64 + wn * 32 + 2 * lt;
        float* row0 = g_t + r0 * 256 + cbase;
        float* row1 = row0 + 8 * 256;
#pragma unroll
        for (int nt = 0; nt < 4; nt++) {
            float2 bv = *(const float2*)(b1 + cbase + nt * 8);
            *(float2*)(row0 + nt * 8) = make_float2(acc[mt][nt][0] + bv.x, acc[mt][nt][1] + bv.y);
            *(float2*)(row1 + nt * 8) = make_float2(acc[mt][nt][2] + bv.x, acc[mt][nt][3] + bv.y);
        }
    }
}

// ---------------- GEMM2: M=64 tiles, grid(2,128) ----------------
__global__ __launch_bounds__(256) void k_gemm2(const float* __restrict__ Wmu,
                                               const float* __restrict__ bmu,
                                               const float* __restrict__ Wls,
                                               const float* __restrict__ bls) {
    __shared__ float As[16 * 64];
    __shared__ float Bs[16 * 64];
    const int bm = blockIdx.y, bn = blockIdx.x;
    const float* W = (bn == 0) ? Wmu : Wls;
    const float* bb = (bn == 0) ? bmu : bls;
    const int tid = threadIdx.x;
    const int ty = tid >> 4, tx = tid & 15;
    const int row0 = ty * 4, col0 = tx * 4;

    unsigned long long acc[2][4];
    {
        float4 bv = *(const float4*)(bb + col0);
        acc[0][0] = dup2(bv.x); acc[0][1] = dup2(bv.y); acc[0][2] = dup2(bv.z); acc[0][3] = dup2(bv.w);
        acc[1][0] = acc[0][0]; acc[1][1] = acc[0][1]; acc[1][2] = acc[0][2]; acc[1][3] = acc[0][3];
    }

    for (int kt = 0; kt < 16; kt++) {
        {
            int ar = tid >> 2, kq = tid & 3;
            float4 v = *(const float4*)(g_h + (size_t)(bm * 64 + ar) * 256 + kt * 16 + kq * 4);
            int rs = ar ^ (kq << 3);
            As[(kq * 4 + 0) * 64 + rs] = v.x;
            As[(kq * 4 + 1) * 64 + rs] = v.y;
            As[(kq * 4 + 2) * 64 + rs] = v.z;
            As[(kq * 4 + 3) * 64 + rs] = v.w;
        }
        {
            int kr = tid >> 4, cq = tid & 15;
            *(float4*)&Bs[kr * 64 + cq * 4] =
                *(const float4*)(W + (size_t)(kt * 16 + kr) * 64 + cq * 4);
        }
        __syncthreads();
#pragma unroll
        for (int k = 0; k < 16; k++) {
            const float* ab = &As[k * 64 + (row0 ^ ((k >> 2) << 3))];
            unsigned long long a0 = *(const unsigned long long*)(ab + 0);
            unsigned long long a1 = *(const unsigned long long*)(ab + 2);
            float4 b = *(const float4*)&Bs[k * 64 + col0];
            unsigned long long bx = dup2(b.x), by = dup2(b.y), bz = dup2(b.z), bw = dup2(b.w);
            ffma2(acc[0][0], a0, bx); ffma2(acc[0][1], a0, by);
            ffma2(acc[0][2], a0, bz); ffma2(acc[0][3], a0, bw);
            ffma2(acc[1][0], a1, bx); ffma2(acc[1][1], a1, by);
            ffma2(acc[1][2], a1, bz); ffma2(acc[1][3], a1, bw);
        }
        __syncthreads();
    }
    float* Cp = g_g + (size_t)(bm * 64 + row0) * 128 + bn * 64 + col0;
#pragma unroll
    for (int p = 0; p < 2; p++) {
        float2 t0 = unpack2(acc[p][0]), t1 = unpack2(acc[p][1]);
        float2 t2 = unpack2(acc[p][2]), t3 = unpack2(acc[p][3]);
        *(float4*)(Cp + (size_t)(2 * p) * 128)     = make_float4(t0.x, t1.x, t2.x, t3.x);
        *(float4*)(Cp + (size_t)(2 * p + 1) * 128) = make_float4(t0.y, t1.y, t2.y, t3.y);
    }
}

// ---------------- SpMM1 + tanh: block 64, float4/thread ----------------
__global__ void k_spmm1() {
    int r = blockIdx.x, tid = threadIdx.x;
    int e = g_cursor[r];
    if (e > RPAD) e = RPAD;
    const int4* cw4 = (const int4*)(g_cw + r * RPAD);
    const float4* T = (const float4*)g_t;
    float4 acc = make_float4(0.f, 0.f, 0.f, 0.f);
    int p = 0;
    for (; p + 8 <= e; p += 8) {
        int4 e01 = cw4[(p >> 1) + 0];
        int4 e23 = cw4[(p >> 1) + 1];
        int4 e45 = cw4[(p >> 1) + 2];
        int4 e67 = cw4[(p >> 1) + 3];
        float4 v0 = T[e01.x * 64 + tid];
        float4 v1 = T[e01.z * 64 + tid];
        float4 v2 = T[e23.x * 64 + tid];
        float4 v3 = T[e23.z * 64 + tid];
        float4 v4 = T[e45.x * 64 + tid];
        float4 v5 = T[e45.z * 64 + tid];
        float4 v6 = T[e67.x * 64 + tid];
        float4 v7 = T[e67.z * 64 + tid];
        float w0 = __int_as_float(e01.y), w1 = __int_as_float(e01.w);
        float w2 = __int_as_float(e23.y), w3 = __int_as_float(e23.w);
        float w4 = __int_as_float(e45.y), w5 = __int_as_float(e45.w);
        float w6 = __int_as_float(e67.y), w7 = __int_as_float(e67.w);
        acc.x = fmaf(w0, v0.x, acc.x); acc.y = fmaf(w0, v0.y, acc.y);
        acc.z = fmaf(w0, v0.z, acc.z); acc.w = fmaf(w0, v0.w, acc.w);
        acc.x = fmaf(w1, v1.x, acc.x); acc.y = fmaf(w1, v1.y, acc.y);
        acc.z = fmaf(w1, v1.z, acc.z); acc.w = fmaf(w1, v1.w, acc.w);
        acc.x = fmaf(w2, v2.x, acc.x); acc.y = fmaf(w2, v2.y, acc.y);
        acc.z = fmaf(w2, v2.z, acc.z); acc.w = fmaf(w2, v2.w, acc.w);
        acc.x = fmaf(w3, v3.x, acc.x); acc.y = fmaf(w3, v3.y, acc.y);
        acc.z = fmaf(w3, v3.z, acc.z); acc.w = fmaf(w3, v3.w, acc.w);
        acc.x = fmaf(w4, v4.x, acc.x); acc.y = fmaf(w4, v4.y, acc.y);
        acc.z = fmaf(w4, v4.z, acc.z); acc.w = fmaf(w4, v4.w, acc.w);
        acc.x = fmaf(w5, v5.x, acc.x); acc.y = fmaf(w5, v5.y, acc.y);
        acc.z = fmaf(w5, v5.z, acc.z); acc.w = fmaf(w5, v5.w, acc.w);
        acc.x = fmaf(w6, v6.x, acc.x); acc.y = fmaf(w6, v6.y, acc.y);
        acc.z = fmaf(w6, v6.z, acc.z); acc.w = fmaf(w6, v6.w, acc.w);
        acc.x = fmaf(w7, v7.x, acc.x); acc.y = fmaf(w7, v7.y, acc.y);
        acc.z = fmaf(w7, v7.z, acc.z); acc.w = fmaf(w7, v7.w, acc.w);
    }
    const int2* cw = g_cw + r * RPAD;
    for (; p < e; p++) {
        int2 a = cw[p];
        float w = __int_as_float(a.y);
        float4 v = T[a.x * 64 + tid];
        acc.x = fmaf(w, v.x, acc.x); acc.y = fmaf(w, v.y, acc.y);
        acc.z = fmaf(w, v.z, acc.z); acc.w = fmaf(w, v.w, acc.w);
    }
    ((float4*)g_h)[r * 64 + tid] =
        make_float4(tanhf(acc.x), tanhf(acc.y), tanhf(acc.z), tanhf(acc.w));
}

// ---------------- SpMM2 + reparam + bf16 split (outputs via .cs) ----------
__global__ void k_spmm2(const float* __restrict__ eps, float* __restrict__ oz,
                        float* __restrict__ omu, float* __restrict__ ols) {
    int r = blockIdx.x, tid = threadIdx.x;
    int e = g_cursor[r];
    if (e > RPAD) e = RPAD;
    const int4* cw4 = (const int4*)(g_cw + r * RPAD);
    const float2* G = (const float2*)g_g;
    float2 acc = make_float2(0.f, 0.f);
    int p = 0;
    for (; p + 8 <= e; p += 8) {
        int4 e01 = cw4[(p >> 1) + 0];
        int4 e23 = cw4[(p >> 1) + 1];
        int4 e45 = cw4[(p >> 1) + 2];
        int4 e67 = cw4[(p >> 1) + 3];
        float2 v0 = G[e01.x * 64 + tid];
        float2 v1 = G[e01.z * 64 + tid];
        float2 v2 = G[e23.x * 64 + tid];
        float2 v3 = G[e23.z * 64 + tid];
        float2 v4 = G[e45.x * 64 + tid];
        float2 v5 = G[e45.z * 64 + tid];
        float2 v6 = G[e67.x * 64 + tid];
        float2 v7 = G[e67.z * 64 + tid];
        float w0 = __int_as_float(e01.y), w1 = __int_as_float(e01.w);
        float w2 = __int_as_float(e23.y), w3 = __int_as_float(e23.w);
        float w4 = __int_as_float(e45.y), w5 = __int_as_float(e45.w);
        float w6 = __int_as_float(e67.y), w7 = __int_as_float(e67.w);
        acc.x = fmaf(w0, v0.x, acc.x); acc.y = fmaf(w0, v0.y, acc.y);
        acc.x = fmaf(w1, v1.x, acc.x); acc.y = fmaf(w1, v1.y, acc.y);
        acc.x = fmaf(w2, v2.x, acc.x); acc.y = fmaf(w2, v2.y, acc.y);
        acc.x = fmaf(w3, v3.x, acc.x); acc.y = fmaf(w3, v3.y, acc.y);
        acc.x = fmaf(w4, v4.x, acc.x); acc.y = fmaf(w4, v4.y, acc.y);
        acc.x = fmaf(w5, v5.x, acc.x); acc.y = fmaf(w5, v5.y, acc.y);
        acc.x = fmaf(w6, v6.x, acc.x); acc.y = fmaf(w6, v6.y, acc.y);
        acc.x = fmaf(w7, v7.x, acc.x); acc.y = fmaf(w7, v7.y, acc.y);
    }
    const int2* cw = g_cw + r * RPAD;
    for (; p < e; p++) {
        int2 a = cw[p];
        float w = __int_as_float(a.y);
        float2 v = G[a.x * 64 + tid];
        acc.x = fmaf(w, v.x, acc.x); acc.y = fmaf(w, v.y, acc.y);
    }
    __shared__ float sm[128];
    sm[2 * tid]     = acc.x;
    sm[2 * tid + 1] = acc.y;
    __syncthreads();
    if (tid < 32) {
        float2 mu = *(const float2*)&sm[2 * tid];
        float2 ls = *(const float2*)&sm[2 * tid + 64];
        float2 ep = ((const float2*)(eps + (size_t)r * 64))[tid];
        float z0 = fmaf(ep.x, expf(ls.x), mu.x);
        float z1 = fmaf(ep.y, expf(ls.y), mu.y);
        stcs2(omu + (size_t)r * 64 + 2 * tid, mu.x, mu.y);
        stcs2(ols + (size_t)r * 64 + 2 * tid, ls.x, ls.y);
        stcs2(oz  + (size_t)r * 64 + 2 * tid, z0, z1);
        __nv_bfloat16 zh0 = __float2bfloat16(z0);
        __nv_bfloat16 zh1 = __float2bfloat16(z1);
        ((__nv_bfloat162*)g_zhi)[r * 32 + tid] = __nv_bfloat162(zh0, zh1);
        ((__nv_bfloat162*)g_zlo)[r * 32 + tid] = __nv_bfloat162(
            __float2bfloat16(z0 - __bfloat162float(zh0)),
            __float2bfloat16(z1 - __bfloat162float(zh1)));
    }
}

// ---------------- z @ z^T: triangular grid, streaming stores ----------------
#define ZZT_SMEM (4 * 16384)
__global__ __launch_bounds__(256, 2) void k_zzt_mma(float* __restrict__ C) {
    extern __shared__ __align__(1024) char smem[];
    char* tAhi = smem;
    char* tAlo = smem + 16384;
    char* tBhi = smem + 32768;
    char* tBlo = smem + 49152;
    int t = blockIdx.x;
    int bi = 0;
    {
        int rem = t;
        while (rem >= 64 - bi) { rem -= 64 - bi; bi++; }
        t = bi + rem;
    }
    const int bj = t;
    const int tid = threadIdx.x, wid = tid >> 5, lid = tid & 31;

    {
        const uint4* ghi_a = (const uint4*)(g_zhi + (size_t)bi * 128 * 64);
        const uint4* glo_a = (const uint4*)(g_zlo + (size_t)bi * 128 * 64);
        const uint4* ghi_b = (const uint4*)(g_zhi + (size_t)bj * 128 * 64);
        const uint4* glo_b = (const uint4*)(g_zlo + (size_t)bj * 128 * 64);
#pragma unroll
        for (int p = 0; p < 4; p++) {
            int idx = tid + p * 256;
            int row = idx >> 3, q = idx & 7;
            uint32_t off = SWZ128((uint32_t)(row * 128 + q * 16));
            *(uint4*)(tAhi + off) = ghi_a[idx];
            *(uint4*)(tAlo + off) = glo_a[idx];
            *(uint4*)(tBhi + off) = ghi_b[idx];
            *(uint4*)(tBlo + off) = glo_b[idx];
        }
    }
    __syncthreads();

    const int wm = wid >> 1, wn = wid & 1;
    const uint32_t sAhi = smem_u32(tAhi), sAlo = smem_u32(tAlo);
    const uint32_t sBhi = smem_u32(tBhi), sBlo = smem_u32(tBlo);

    float acc[2][8][4];
#pragma unroll
    for (int mt = 0; mt < 2; mt++)
#pragma unroll
        for (int nt = 0; nt < 8; nt++)
#pragma unroll
            for (int r = 0; r < 4; r++) acc[mt][nt][r] = 0.f;

    const int l7 = lid & 7, g2 = lid >> 3;

#pragma unroll
    for (int ks = 0; ks < 4; ks++) {
        uint32_t ahi[2][4], alo[2][4];
#pragma unroll
        for (int mt = 0; mt < 2; mt++) {
            int row = wm * 32 + mt * 16 + ((g2 & 1) << 3) + l7;
            int q   = ks * 2 + (g2 >> 1);
            uint32_t off = SWZ128((uint32_t)(row * 128 + q * 16));
            ldsm4(ahi[mt][0], ahi[mt][1], ahi[mt][2], ahi[mt][3], sAhi + off);
            ldsm4(alo[mt][0], alo[mt][1], alo[mt][2], alo[mt][3], sAlo + off);
        }
#pragma unroll
        for (int ntp = 0; ntp < 4; ntp++) {
            int nrow = wn * 64 + ntp * 16 + ((g2 >> 1) << 3) + l7;
            int q    = ks * 2 + (g2 & 1);
            uint32_t off = SWZ128((uint32_t)(nrow * 128 + q * 16));
            uint32_t bh[4], bl[4];
            ldsm4(bh[0], bh[1], bh[2], bh[3], sBhi + off);
            ldsm4(bl[0], bl[1], bl[2], bl[3], sBlo + off);
            int nt0 = ntp * 2, nt1 = ntp * 2 + 1;
#pragma unroll
            for (int mt = 0; mt < 2; mt++) {
                mma16816(acc[mt][nt0], ahi[mt], bh + 0);
                mma16816(acc[mt][nt1], ahi[mt], bh + 2);
                mma16816(acc[mt][nt0], ahi[mt], bl + 0);
                mma16816(acc[mt][nt1], ahi[mt], bl + 2);
                mma16816(acc[mt][nt0], alo[mt], bh + 0);
                mma16816(acc[mt][nt1], alo[mt], bh + 2);
            }
        }
    }

    const int lg = lid >> 2, lt = lid & 3;
#pragma unroll
    for (int mt = 0; mt < 2; mt++) {
        size_t r0 = (size_t)(bi * 128 + wm * 32 + mt * 16 + lg);
        float* row0 = C + r0 * NROW + bj * 128 + wn * 64 + 2 * lt;
        float* row1 = row0 + 8 * (size_t)NROW;
#pragma unroll
        for (int nt = 0; nt < 8; nt++) {
            stcs2(row0 + nt * 8, acc[mt][nt][0], acc[mt][nt][1]);
            stcs2(row1 + nt * 8, acc[mt][nt][2], acc[mt][nt][3]);
        }
    }

    if (bi != bj) {
        __syncthreads();
        float* smT = (float*)smem;
#pragma unroll
        for (int mt = 0; mt < 2; mt++) {
#pragma unroll
            for (int nt = 0; nt < 8; nt++) {
#pragma unroll
                for (int r = 0; r < 4; r++) {
                    int ri = wm * 32 + mt * 16 + lg + ((r >> 1) << 3);
                    int cj = wn * 64 + nt * 8 + 2 * lt + (r & 1);
                    smT[cj * 128 + (ri ^ ((cj & 7) << 3))] = acc[mt][nt][r];
                }
            }
        }
        __syncthreads();
#pragma unroll
        for (int p = 0; p < 16; p++) {
            int idx = tid + p * 256;
            int mr = idx >> 5, q = idx & 31;
            int ri0 = (q * 4) ^ ((mr & 7) << 3);
            float4 v = *(const float4*)&smT[mr * 128 + ri0];
            stcs4(C + (size_t)(bj * 128 + mr) * NROW + bi * 128 + (q * 4), v);
        }
    }
}

// ---------------- launch (R14 schedule: single fork gemm1 || scatter) ----------
extern "C" void kernel_launch(void* const* d_in, const int* in_sizes, int n_in,
                              void* d_out, int out_size) {
    const float* x    = (const float*)d_in[0];
    const int*   esrc = (const int*)d_in[1];
    const int*   edst = (const int*)d_in[2];
    const float* ew   = (const float*)d_in[3];
    const float* eps  = (const float*)d_in[4];
    const float* W1   = (const float*)d_in[5];
    const float* b1   = (const float*)d_in[6];
    const float* Wmu  = (const float*)d_in[7];
    const float* bmu  = (const float*)d_in[8];
    const float* Wls  = (const float*)d_in[9];
    const float* bls  = (const float*)d_in[10];

    float* out  = (float*)d_out;
    float* oz   = out;
    float* oadj = out + (size_t)NROW * 64;
    float* omu  = oadj + (size_t)NROW * NROW;
    float* ols  = omu + (size_t)NROW * 64;

    cudaFuncSetAttribute(k_zzt_mma, cudaFuncAttributeMaxDynamicSharedMemorySize, ZZT_SMEM);
    cudaFuncSetAttribute(k_gemm1_mma, cudaFuncAttributeMaxDynamicSharedMemorySize, G1_SMEM);

    k_prep<<<512, 256>>>(W1);

    cudaEventRecord(g_evF, 0);
    cudaStreamWaitEvent(g_s2, g_evF, 0);
    k_gemm1_mma<<<dim3(4, 64), 256, G1_SMEM, g_s2>>>(x, b1);
    k_scatter_pad<<<NE / 256, 256>>>(esrc, edst, ew);
    cudaEventRecord(g_evJ, g_s2);
    cudaStreamWaitEvent(0, g_evJ, 0);

    k_spmm1<<<NROW, 64>>>();
    k_gemm2<<<dim3(2, 128), 256>>>(Wmu, bmu, Wls, bls);
    k_spmm2<<<NROW, 64>>>(eps, oz, omu, ols);
    k_zzt_mma<<<64 * 65 / 2, 256, ZZT_SMEM>>>(oadj);
}